// round 13
// baseline (speedup 1.0000x reference)
#include <cuda_runtime.h>
#include <cuda_bf16.h>
#include <math.h>
#include <stdint.h>

#define N_NODES 50000
#define N_EDGES 800000
#define D 64
#define SBLK 250
#define SNPB 200

// fragment geometry (word = 4 bytes)
#define A_KT_STRIDE 1032          // 128 rows * 8 words + 8 pad
#define W_KT_STRIDE 520           // 64 rows * 8 words + 8 pad
#define W_WORDS (4 * W_KT_STRIDE) // 2080 words per matrix per half

// k_node smem layout
#define OFS_AH 0                  // 16512 B
#define OFS_AL 16512
#define OFS_WH 33024              // 8320 B
#define OFS_WL 41344
#define OFS_AUX 49664
#define NODE_SMEM (49664 + 2048)

// k_edge smem layout: W persists across 2 tiles; sD has own region
#define EOFS_WH 0                 // 8320 B
#define EOFS_WL 8320              // 8320 B
#define EOFS_SD 16640             // 128 x 68 f32 = 34816 B
#define EOFS_AUX 51456            // bias 256, wa 256, ssend 1024, srecv 1024
#define EDGE_SMEM (51456 + 2560)  // 54016 B -> 4 blocks/SM = 216 KB

// ---------------- scratch ----------------
__device__ float    g_sent[N_NODES * D];
__device__ float    g_recv[N_NODES * D];
__device__ float    g_msg [N_NODES * D];
__device__ float    g_elogit[N_EDGES];   // exp(leaky_relu(logit))
__device__ int      g_count[N_NODES];
__device__ int      g_part[SBLK];
__device__ int      g_rowoff[N_NODES + 1];
__device__ int      g_cursor[N_NODES];
__device__ int2     g_csr_sw[N_EDGES];   // (sender, exp-logit bits) in CSR order
__device__ unsigned g_wpH[5][W_WORDS];
__device__ unsigned g_wpL[5][W_WORDS];

// ---------------- bf16 helpers ----------------
__device__ __forceinline__ void cvt2(float2 v, unsigned& h, unsigned& l) {
    __nv_bfloat16 b0 = __float2bfloat16(v.x), b1 = __float2bfloat16(v.y);
    h = (unsigned)__bfloat16_as_ushort(b0) | ((unsigned)__bfloat16_as_ushort(b1) << 16);
    __nv_bfloat16 r0 = __float2bfloat16(v.x - __bfloat162float(b0));
    __nv_bfloat16 r1 = __float2bfloat16(v.y - __bfloat162float(b1));
    l = (unsigned)__bfloat16_as_ushort(r0) | ((unsigned)__bfloat16_as_ushort(r1) << 16);
}

#define MMAB(d, a0, a1, a2, a3, b0, b1) \
    asm volatile("mma.sync.aligned.m16n8k16.row.col.f32.bf16.bf16.f32 " \
                 "{%0,%1,%2,%3}, {%4,%5,%6,%7}, {%8,%9}, {%0,%1,%2,%3};" \
                 : "+f"((d)[0]), "+f"((d)[1]), "+f"((d)[2]), "+f"((d)[3]) \
                 : "r"(a0), "r"(a1), "r"(a2), "r"(a3), "r"(b0), "r"(b1))

// ---------------- K1: pre-pack weight fragments ----------------
__global__ void k_prep(const float* __restrict__ Ws, const float* __restrict__ Wr,
                       const float* __restrict__ Wm, const float* __restrict__ Wf,
                       const float* __restrict__ We) {
    const float* Wl[5] = {Ws, Wr, Wm, Wf, We};
    int m = blockIdx.x;
    const float4* W4 = (const float4*)Wl[m];
    int tx = threadIdx.x;
    for (int i = tx; i < 64 * 16; i += 256) {
        int k = i >> 4, n0 = (i & 15) * 4;
        float4 v = W4[i];
        float vv[4] = {v.x, v.y, v.z, v.w};
        int kt = k >> 4, kk = k & 15;
        int c = kk >> 3, q = (kk & 7) >> 1, p = kk & 1;
        #pragma unroll
        for (int j = 0; j < 4; j++) {
            int n = n0 + j;
            __nv_bfloat16 hb = __float2bfloat16(vv[j]);
            __nv_bfloat16 lb = __float2bfloat16(vv[j] - __bfloat162float(hb));
            int word = kt * W_KT_STRIDE + n * 8 + ((c * 4 + q) ^ (n & 6));
            ((unsigned short*)&g_wpH[m][word])[p] = __bfloat16_as_ushort(hb);
            ((unsigned short*)&g_wpL[m][word])[p] = __bfloat16_as_ushort(lb);
        }
    }
}

// ---------------- K2: init ----------------
__global__ void k_init() {
    int i = blockIdx.x * blockDim.x + threadIdx.x;
    if (i < N_NODES) g_count[i] = 0;
}

// ---------------- A packing into smem (k_node; A reused 4x) ----------------
__device__ __forceinline__ void pack_A4(char* sm, int row, int c4, float4 v) {
    float2 v01 = make_float2(v.x, v.y), v23 = make_float2(v.z, v.w);
    unsigned h01, l01, h23, l23;
    cvt2(v01, h01, l01); cvt2(v23, h23, l23);
    int kt = c4 >> 2, kk = (c4 & 3) * 4;
    int c = kk >> 3, q0 = (kk & 7) >> 1;
    int sw = (c * 4 + q0) ^ (row & 6);
    int base = kt * A_KT_STRIDE + row * 8 + sw;
    *(uint2*)((unsigned*)(sm + OFS_AH) + base) = make_uint2(h01, h23);
    *(uint2*)((unsigned*)(sm + OFS_AL) + base) = make_uint2(l01, l23);
}

// ---------------- warp MMA from smem A + smem W (k_node) ----------------
__device__ __forceinline__ void mma_tile_smemA(const char* sm, int lane, int w,
                                               float acc[2][4][4]) {
    const unsigned* AH = (const unsigned*)(sm + OFS_AH);
    const unsigned* AL = (const unsigned*)(sm + OFS_AL);
    const unsigned* WH = (const unsigned*)(sm + OFS_WH);
    const unsigned* WL = (const unsigned*)(sm + OFS_WL);
    int g = lane >> 2, q = lane & 3;
    int s6 = g & 6;
    int wlo = q ^ s6, whi = (4 + q) ^ s6;
    int mtb = (w & 3) * 32, nb = (w >> 2) * 32;
    #pragma unroll
    for (int mt = 0; mt < 2; mt++)
        #pragma unroll
        for (int nt = 0; nt < 4; nt++)
            #pragma unroll
            for (int j = 0; j < 4; j++) acc[mt][nt][j] = 0.f;

    #pragma unroll
    for (int kt = 0; kt < 4; kt++) {
        unsigned ah[2][4], al[2][4];
        #pragma unroll
        for (int mt = 0; mt < 2; mt++) {
            int r0 = mtb + mt * 16 + g;
            int b0 = kt * A_KT_STRIDE + r0 * 8;
            int b1 = b0 + 64;
            ah[mt][0] = AH[b0 + wlo]; ah[mt][1] = AH[b1 + wlo];
            ah[mt][2] = AH[b0 + whi]; ah[mt][3] = AH[b1 + whi];
            al[mt][0] = AL[b0 + wlo]; al[mt][1] = AL[b1 + wlo];
            al[mt][2] = AL[b0 + whi]; al[mt][3] = AL[b1 + whi];
        }
        #pragma unroll
        for (int nt = 0; nt < 4; nt++) {
            int n = nb + nt * 8 + g;
            int wb = kt * W_KT_STRIDE + n * 8;
            unsigned bh0 = WH[wb + wlo], bh1 = WH[wb + whi];
            unsigned bl0 = WL[wb + wlo], bl1 = WL[wb + whi];
            #pragma unroll
            for (int mt = 0; mt < 2; mt++) {
                MMAB(acc[mt][nt], ah[mt][0], ah[mt][1], ah[mt][2], ah[mt][3], bh0, bh1);
                MMAB(acc[mt][nt], ah[mt][0], ah[mt][1], ah[mt][2], ah[mt][3], bl0, bl1);
                MMAB(acc[mt][nt], al[mt][0], al[mt][1], al[mt][2], al[mt][3], bh0, bh1);
            }
        }
    }
}

// ---------------- K3: node projections ----------------
__global__ void __launch_bounds__(256, 4) k_node(
    const float* __restrict__ nodes,
    const float* __restrict__ bs, const float* __restrict__ br,
    const float* __restrict__ bm, const float* __restrict__ bf,
    float* __restrict__ out_self)
{
    extern __shared__ char sm[];
    int tx = threadIdx.x, w = tx >> 5, lane = tx & 31;
    int n0 = blockIdx.x * 128;

    const float4* nd4 = (const float4*)nodes;
    for (int i = tx; i < 128 * 16; i += 256) {
        int row = i >> 4, c4 = i & 15;
        float4 v = make_float4(0.f, 0.f, 0.f, 0.f);
        int gr = n0 + row;
        if (gr < N_NODES) v = nd4[(size_t)gr * 16 + c4];
        pack_A4(sm, row, c4, v);
    }
    float* sbias = (float*)(sm + OFS_AUX);
    if (tx < 64) {
        sbias[tx] = bs[tx]; sbias[64 + tx] = br[tx];
        sbias[128 + tx] = bm[tx]; sbias[192 + tx] = bf[tx];
    }

    float* olist[4] = {g_sent, g_recv, g_msg, out_self};
    int g = lane >> 2, q = lane & 3;
    int mtb = (w & 3) * 32, nb = (w >> 2) * 32;

    #pragma unroll
    for (int m = 0; m < 4; m++) {
        __syncthreads();
        for (int i = tx; i < W_WORDS / 4; i += 256) {
            ((uint4*)(sm + OFS_WH))[i] = ((const uint4*)&g_wpH[m][0])[i];
            ((uint4*)(sm + OFS_WL))[i] = ((const uint4*)&g_wpL[m][0])[i];
        }
        __syncthreads();

        float acc[2][4][4];
        mma_tile_smemA(sm, lane, w, acc);

        float* out = olist[m];
        const float* bi = sbias + m * 64;
        #pragma unroll
        for (int mt = 0; mt < 2; mt++) {
            int gr0 = n0 + mtb + mt * 16 + g;
            int gr1 = gr0 + 8;
            #pragma unroll
            for (int nt = 0; nt < 4; nt++) {
                int c = nb + nt * 8 + q * 2;
                float bx = bi[c], by = bi[c + 1];
                if (gr0 < N_NODES)
                    *(float2*)&out[(size_t)gr0 * 64 + c] =
                        make_float2(acc[mt][nt][0] + bx, acc[mt][nt][1] + by);
                if (gr1 < N_NODES)
                    *(float2*)&out[(size_t)gr1 * 64 + c] =
                        make_float2(acc[mt][nt][2] + bx, acc[mt][nt][3] + by);
            }
        }
    }
}

// ---------------- K4: edge GEMM, 2 tiles per block (W resident) ----------------
__global__ void __launch_bounds__(256, 4) k_edge(
    const float* __restrict__ edges,
    const int* __restrict__ senders, const int* __restrict__ receivers,
    const float* __restrict__ b_edge, const float* __restrict__ W_attn,
    const float* __restrict__ b_attn,
    float* __restrict__ edge_feat)
{
    extern __shared__ char sm[];
    int tx = threadIdx.x, w = tx >> 5, lane = tx & 31;
    int e0b = blockIdx.x * 256;

    float* sbw   = (float*)(sm + EOFS_AUX);        // [0:64) bias, [64:128) wa
    int*   ssend = (int*)(sm + EOFS_AUX + 512);    // 256 ints
    int*   srecv = (int*)(sm + EOFS_AUX + 1536);   // 256 ints

    ssend[tx] = senders[e0b + tx];
    srecv[tx] = receivers[e0b + tx];
    if (tx < 64) { sbw[tx] = b_edge[tx]; sbw[64 + tx] = W_attn[tx]; }
    for (int i = tx; i < W_WORDS / 4; i += 256) {
        ((uint4*)(sm + EOFS_WH))[i] = ((const uint4*)&g_wpH[4][0])[i];
        ((uint4*)(sm + EOFS_WL))[i] = ((const uint4*)&g_wpL[4][0])[i];
    }
    __syncthreads();

    const unsigned* WH = (const unsigned*)(sm + EOFS_WH);
    const unsigned* WL = (const unsigned*)(sm + EOFS_WL);
    float* sD = (float*)(sm + EOFS_SD);             // 128 x 68

    int g = lane >> 2, q = lane & 3;
    int s6 = g & 6;
    int wlo = q ^ s6, whi = (4 + q) ^ s6;
    int mtb = (w & 3) * 32, nb = (w >> 2) * 32;
    int cr = tx & 15, rbase = tx >> 4;
    int c0 = cr * 4;
    float4 bi = *(float4*)&sbw[c0];
    float4 wa = *(float4*)&sbw[64 + c0];
    float battn = b_attn[0];

    #pragma unroll
    for (int t = 0; t < 2; t++) {
        int e0 = e0b + t * 128;
        const float2* eg2 = (const float2*)(edges + (size_t)e0 * 64);

        float acc[2][4][4];
        #pragma unroll
        for (int mt = 0; mt < 2; mt++)
            #pragma unroll
            for (int nt = 0; nt < 4; nt++)
                #pragma unroll
                for (int j = 0; j < 4; j++) acc[mt][nt][j] = 0.f;

        #pragma unroll
        for (int kt = 0; kt < 4; kt++) {
            unsigned ah[2][4], al[2][4];
            #pragma unroll
            for (int mt = 0; mt < 2; mt++) {
                int r0 = mtb + mt * 16 + g;
                int base = r0 * 32 + kt * 8 + q;
                float2 v00 = eg2[base];
                float2 v01 = eg2[base + 4];
                float2 v10 = eg2[base + 256];
                float2 v11 = eg2[base + 260];
                cvt2(v00, ah[mt][0], al[mt][0]);
                cvt2(v10, ah[mt][1], al[mt][1]);
                cvt2(v01, ah[mt][2], al[mt][2]);
                cvt2(v11, ah[mt][3], al[mt][3]);
            }
            #pragma unroll
            for (int nt = 0; nt < 4; nt++) {
                int n = nb + nt * 8 + g;
                int wb = kt * W_KT_STRIDE + n * 8;
                unsigned bh0 = WH[wb + wlo], bh1 = WH[wb + whi];
                unsigned bl0 = WL[wb + wlo], bl1 = WL[wb + whi];
                #pragma unroll
                for (int mt = 0; mt < 2; mt++) {
                    MMAB(acc[mt][nt], ah[mt][0], ah[mt][1], ah[mt][2], ah[mt][3], bh0, bh1);
                    MMAB(acc[mt][nt], ah[mt][0], ah[mt][1], ah[mt][2], ah[mt][3], bl0, bl1);
                    MMAB(acc[mt][nt], al[mt][0], al[mt][1], al[mt][2], al[mt][3], bh0, bh1);
                }
            }
        }
        __syncthreads();     // tile t-1 epilogue readers of sD done (and tile-0 W copy ordering)

        #pragma unroll
        for (int mt = 0; mt < 2; mt++) {
            int r0 = mtb + mt * 16 + g;
            #pragma unroll
            for (int nt = 0; nt < 4; nt++) {
                int c = nb + nt * 8 + q * 2;
                *(float2*)&sD[r0 * 68 + c]       = make_float2(acc[mt][nt][0], acc[mt][nt][1]);
                *(float2*)&sD[(r0 + 8) * 68 + c] = make_float2(acc[mt][nt][2], acc[mt][nt][3]);
            }
        }
        __syncthreads();

        // 16 threads per row -> contiguous 256B gathers/stores per row
        #pragma unroll
        for (int i = 0; i < 8; i++) {
            int row = rbase + i * 16;
            int e = e0 + row;
            int s = ssend[t * 128 + row], r = srecv[t * 128 + row];
            float4 sv = *(const float4*)(g_sent + (size_t)s * 64 + c0);
            float4 rv = *(const float4*)(g_recv + (size_t)r * 64 + c0);
            float4 d  = *(const float4*)&sD[row * 68 + c0];

            float4 ef;
            ef.x = d.x + bi.x + sv.x + rv.x;
            ef.y = d.y + bi.y + sv.y + rv.y;
            ef.z = d.z + bi.z + sv.z + rv.z;
            ef.w = d.w + bi.w + sv.w + rv.w;
            *(float4*)&edge_feat[(size_t)e * 64 + c0] = ef;

            float p = ef.x * wa.x + ef.y * wa.y + ef.z * wa.z + ef.w * wa.w;
            p += __shfl_xor_sync(0xffffffffu, p, 1);
            p += __shfl_xor_sync(0xffffffffu, p, 2);
            p += __shfl_xor_sync(0xffffffffu, p, 4);
            p += __shfl_xor_sync(0xffffffffu, p, 8);
            if (cr == 0) {
                float l = p + battn;
                l = (l > 0.f) ? l : 0.01f * l;      // leaky_relu slope 0.01
                g_elogit[e] = __expf(l);            // max-free softmax (bounded logits)
                atomicAdd(&g_count[r], 1);
            }
        }
    }
}

// ---------------- scan ----------------
__global__ void k_scan_a() {
    __shared__ int red[256];
    int b = blockIdx.x, t = threadIdx.x;
    red[t] = (t < SNPB) ? g_count[b * SNPB + t] : 0;
    __syncthreads();
    for (int off = 128; off; off >>= 1) {
        if (t < off) red[t] += red[t + off];
        __syncthreads();
    }
    if (t == 0) g_part[b] = red[0];
}
__global__ void k_scan_c() {
    __shared__ int sbase[256];
    __shared__ int sc[256];
    int b = blockIdx.x, t = threadIdx.x;
    sbase[t] = (t < b) ? g_part[t] : 0;
    __syncthreads();
    for (int off = 128; off; off >>= 1) {
        if (t < off) sbase[t] += sbase[t + off];
        __syncthreads();
    }
    int base = sbase[0];
    int idx = b * SNPB + t;
    int c = (t < SNPB) ? g_count[idx] : 0;
    sc[t] = c;
    __syncthreads();
    for (int off = 1; off < 256; off <<= 1) {
        int v = 0;
        if (t >= off) v = sc[t - off];
        __syncthreads();
        if (t >= off) sc[t] += v;
        __syncthreads();
    }
    if (t < SNPB) {
        int ro = base + sc[t] - c;
        g_rowoff[idx] = ro;
        g_cursor[idx] = ro;
    }
    if (b == SBLK - 1 && t == SNPB - 1) g_rowoff[N_NODES] = base + sc[t];
}

// ---------------- K7: CSR fill (packed sender+weight, one 8B store) ----------------
__global__ void k_fill(const int* __restrict__ senders,
                       const int* __restrict__ receivers) {
    int e = blockIdx.x * blockDim.x + threadIdx.x;
    if (e < N_EDGES) {
        int r = receivers[e];
        int s = senders[e];
        float w = g_elogit[e];
        int slot = atomicAdd(&g_cursor[r], 1);
        g_csr_sw[slot] = make_int2(s, __float_as_int(w));
    }
}

// ---------------- K8: warp-per-node aggregation (unrolled, packed CSR) ----------------
__global__ void k_aggregate(float* __restrict__ out_nodes)
{
    int gid = blockIdx.x * blockDim.x + threadIdx.x;
    int n = gid >> 5;
    if (n >= N_NODES) return;
    int lane = gid & 31;
    int off = g_rowoff[n];
    int deg = g_rowoff[n + 1] - off;

    int half = lane >> 4, quad = lane & 15;
    float4 acc = make_float4(0.f, 0.f, 0.f, 0.f);
    float sumex = 0.f;
    const float4* msg4 = (const float4*)g_msg;

    int t = half;
    for (; t + 2 < deg; t += 4) {          // two edges per iteration (MLP=2)
        int2 a = g_csr_sw[off + t];
        int2 b = g_csr_sw[off + t + 2];
        float exa = __int_as_float(a.y), exb = __int_as_float(b.y);
        float4 ma = msg4[(size_t)a.x * 16 + quad];
        float4 mb = msg4[(size_t)b.x * 16 + quad];
        acc.x += exa * ma.x + exb * mb.x;
        acc.y += exa * ma.y + exb * mb.y;
        acc.z += exa * ma.z + exb * mb.z;
        acc.w += exa * ma.w + exb * mb.w;
        if (quad == 0) sumex += exa + exb;
    }
    if (t < deg) {
        int2 a = g_csr_sw[off + t];
        float exa = __int_as_float(a.y);
        float4 ma = msg4[(size_t)a.x * 16 + quad];
        acc.x += exa * ma.x; acc.y += exa * ma.y;
        acc.z += exa * ma.z; acc.w += exa * ma.w;
        if (quad == 0) sumex += exa;
    }

    acc.x += __shfl_xor_sync(0xffffffffu, acc.x, 16);
    acc.y += __shfl_xor_sync(0xffffffffu, acc.y, 16);
    acc.z += __shfl_xor_sync(0xffffffffu, acc.z, 16);
    acc.w += __shfl_xor_sync(0xffffffffu, acc.w, 16);
    sumex += __shfl_xor_sync(0xffffffffu, sumex, 16);
    sumex = __shfl_sync(0xffffffffu, sumex, 0);

    if (lane < 16) {
        float inv = (deg > 0) ? (1.f / sumex) : 0.f;
        float4* o4 = (float4*)out_nodes;
        float4 o = o4[(size_t)n * 16 + lane];
        o.x += acc.x * inv; o.y += acc.y * inv;
        o.z += acc.z * inv; o.w += acc.w * inv;
        o4[(size_t)n * 16 + lane] = o;
    }
}

// ---------------- launch ----------------
extern "C" void kernel_launch(void* const* d_in, const int* in_sizes, int n_in,
                              void* d_out, int out_size)
{
    const float* nodes     = (const float*)d_in[0];
    const float* edges     = (const float*)d_in[1];
    const int*   senders   = (const int*)  d_in[2];
    const int*   receivers = (const int*)  d_in[3];
    const float* W_sent = (const float*)d_in[4];  const float* b_sent = (const float*)d_in[5];
    const float* W_recv = (const float*)d_in[6];  const float* b_recv = (const float*)d_in[7];
    const float* W_edge = (const float*)d_in[8];  const float* b_edge = (const float*)d_in[9];
    const float* W_attn = (const float*)d_in[10]; const float* b_attn = (const float*)d_in[11];
    const float* W_msg  = (const float*)d_in[12]; const float* b_msg  = (const float*)d_in[13];
    const float* W_self = (const float*)d_in[14]; const float* b_self = (const float*)d_in[15];

    float* out_nodes = (float*)d_out;
    float* edge_feat = out_nodes + (size_t)N_NODES * D;

    cudaFuncSetAttribute(k_node, cudaFuncAttributeMaxDynamicSharedMemorySize, NODE_SMEM);
    cudaFuncSetAttribute(k_edge, cudaFuncAttributeMaxDynamicSharedMemorySize, EDGE_SMEM);

    // launch #4 gets ncu-profiled -> keep k_edge there
    k_prep<<<5, 256>>>(W_sent, W_recv, W_msg, W_self, W_edge);      // 1
    k_init<<<(N_NODES + 255) / 256, 256>>>();                       // 2
    k_node<<<(N_NODES + 127) / 128, 256, NODE_SMEM>>>(              // 3
        nodes, b_sent, b_recv, b_msg, b_self, out_nodes);
    k_edge<<<N_EDGES / 256, 256, EDGE_SMEM>>>(                      // 4  <- profiled
        edges, senders, receivers, b_edge, W_attn, b_attn, edge_feat);
    k_scan_a<<<SBLK, 256>>>();                                      // 5
    k_scan_c<<<SBLK, 256>>>();                                      // 6
    k_fill<<<N_EDGES / 256, 256>>>(senders, receivers);             // 7
    k_aggregate<<<(N_NODES * 32 + 255) / 256, 256>>>(out_nodes);    // 8
}

// round 14
// speedup vs baseline: 1.2141x; 1.2141x over previous
#include <cuda_runtime.h>
#include <cuda_bf16.h>
#include <math.h>
#include <stdint.h>

#define N_NODES 50000
#define N_EDGES 800000
#define D 64
#define SBLK 250
#define SNPB 200

// fragment geometry (word = 4 bytes)
#define A_KT_STRIDE 1032          // 128 rows * 8 words + 8 pad
#define W_KT_STRIDE 520           // 64 rows * 8 words + 8 pad
#define W_WORDS (4 * W_KT_STRIDE) // 2080 words per matrix per half

// k_node smem layout
#define OFS_AH 0                  // 16512 B
#define OFS_AL 16512
#define OFS_WH 33024              // 8320 B
#define OFS_WL 41344
#define OFS_AUX 49664
#define NODE_SMEM (49664 + 2048)

// k_edge smem layout (single tile; sD aliases W region after MMA)
#define EOFS_WH 0                 // 8320 B
#define EOFS_WL 8320              // 8320 B
#define EOFS_SD 0                 // 128 x 68 f32 = 34816 B (aliases W, post-MMA)
#define EOFS_AUX 34816            // 2048 B
#define EDGE_SMEM (34816 + 2048)

// ---------------- scratch ----------------
__device__ float    g_sent[N_NODES * D];
__device__ float    g_recv[N_NODES * D];
__device__ float    g_msg [N_NODES * D];
__device__ float    g_elogit[N_EDGES];   // exp(leaky_relu(logit))
__device__ int      g_count[N_NODES];
__device__ int      g_part[SBLK];
__device__ int      g_rowoff[N_NODES + 1];
__device__ int      g_cursor[N_NODES];
__device__ int2     g_csr_sw[N_EDGES];   // (sender, exp-logit bits) in CSR order
__device__ unsigned g_wpH[5][W_WORDS];
__device__ unsigned g_wpL[5][W_WORDS];

// ---------------- bf16 helpers ----------------
__device__ __forceinline__ void cvt2(float2 v, unsigned& h, unsigned& l) {
    __nv_bfloat16 b0 = __float2bfloat16(v.x), b1 = __float2bfloat16(v.y);
    h = (unsigned)__bfloat16_as_ushort(b0) | ((unsigned)__bfloat16_as_ushort(b1) << 16);
    __nv_bfloat16 r0 = __float2bfloat16(v.x - __bfloat162float(b0));
    __nv_bfloat16 r1 = __float2bfloat16(v.y - __bfloat162float(b1));
    l = (unsigned)__bfloat16_as_ushort(r0) | ((unsigned)__bfloat16_as_ushort(r1) << 16);
}

#define MMAB(d, a0, a1, a2, a3, b0, b1) \
    asm volatile("mma.sync.aligned.m16n8k16.row.col.f32.bf16.bf16.f32 " \
                 "{%0,%1,%2,%3}, {%4,%5,%6,%7}, {%8,%9}, {%0,%1,%2,%3};" \
                 : "+f"((d)[0]), "+f"((d)[1]), "+f"((d)[2]), "+f"((d)[3]) \
                 : "r"(a0), "r"(a1), "r"(a2), "r"(a3), "r"(b0), "r"(b1))

// ---------------- K1: pre-pack weight fragments ----------------
__global__ void k_prep(const float* __restrict__ Ws, const float* __restrict__ Wr,
                       const float* __restrict__ Wm, const float* __restrict__ Wf,
                       const float* __restrict__ We) {
    const float* Wl[5] = {Ws, Wr, Wm, Wf, We};
    int m = blockIdx.x;
    const float4* W4 = (const float4*)Wl[m];
    int tx = threadIdx.x;
    for (int i = tx; i < 64 * 16; i += 256) {
        int k = i >> 4, n0 = (i & 15) * 4;
        float4 v = W4[i];
        float vv[4] = {v.x, v.y, v.z, v.w};
        int kt = k >> 4, kk = k & 15;
        int c = kk >> 3, q = (kk & 7) >> 1, p = kk & 1;
        #pragma unroll
        for (int j = 0; j < 4; j++) {
            int n = n0 + j;
            __nv_bfloat16 hb = __float2bfloat16(vv[j]);
            __nv_bfloat16 lb = __float2bfloat16(vv[j] - __bfloat162float(hb));
            int word = kt * W_KT_STRIDE + n * 8 + ((c * 4 + q) ^ (n & 6));
            ((unsigned short*)&g_wpH[m][word])[p] = __bfloat16_as_ushort(hb);
            ((unsigned short*)&g_wpL[m][word])[p] = __bfloat16_as_ushort(lb);
        }
    }
}

// ---------------- K2: init ----------------
__global__ void k_init() {
    int i = blockIdx.x * blockDim.x + threadIdx.x;
    if (i < N_NODES) g_count[i] = 0;
}

// ---------------- A packing into smem (k_node; A reused 4x) ----------------
__device__ __forceinline__ void pack_A4(char* sm, int row, int c4, float4 v) {
    float2 v01 = make_float2(v.x, v.y), v23 = make_float2(v.z, v.w);
    unsigned h01, l01, h23, l23;
    cvt2(v01, h01, l01); cvt2(v23, h23, l23);
    int kt = c4 >> 2, kk = (c4 & 3) * 4;
    int c = kk >> 3, q0 = (kk & 7) >> 1;
    int sw = (c * 4 + q0) ^ (row & 6);
    int base = kt * A_KT_STRIDE + row * 8 + sw;
    *(uint2*)((unsigned*)(sm + OFS_AH) + base) = make_uint2(h01, h23);
    *(uint2*)((unsigned*)(sm + OFS_AL) + base) = make_uint2(l01, l23);
}

// ---------------- warp MMA from smem A + smem W (k_node) ----------------
__device__ __forceinline__ void mma_tile_smemA(const char* sm, int lane, int w,
                                               float acc[2][4][4]) {
    const unsigned* AH = (const unsigned*)(sm + OFS_AH);
    const unsigned* AL = (const unsigned*)(sm + OFS_AL);
    const unsigned* WH = (const unsigned*)(sm + OFS_WH);
    const unsigned* WL = (const unsigned*)(sm + OFS_WL);
    int g = lane >> 2, q = lane & 3;
    int s6 = g & 6;
    int wlo = q ^ s6, whi = (4 + q) ^ s6;
    int mtb = (w & 3) * 32, nb = (w >> 2) * 32;
    #pragma unroll
    for (int mt = 0; mt < 2; mt++)
        #pragma unroll
        for (int nt = 0; nt < 4; nt++)
            #pragma unroll
            for (int j = 0; j < 4; j++) acc[mt][nt][j] = 0.f;

    #pragma unroll
    for (int kt = 0; kt < 4; kt++) {
        unsigned ah[2][4], al[2][4];
        #pragma unroll
        for (int mt = 0; mt < 2; mt++) {
            int r0 = mtb + mt * 16 + g;
            int b0 = kt * A_KT_STRIDE + r0 * 8;
            int b1 = b0 + 64;
            ah[mt][0] = AH[b0 + wlo]; ah[mt][1] = AH[b1 + wlo];
            ah[mt][2] = AH[b0 + whi]; ah[mt][3] = AH[b1 + whi];
            al[mt][0] = AL[b0 + wlo]; al[mt][1] = AL[b1 + wlo];
            al[mt][2] = AL[b0 + whi]; al[mt][3] = AL[b1 + whi];
        }
        #pragma unroll
        for (int nt = 0; nt < 4; nt++) {
            int n = nb + nt * 8 + g;
            int wb = kt * W_KT_STRIDE + n * 8;
            unsigned bh0 = WH[wb + wlo], bh1 = WH[wb + whi];
            unsigned bl0 = WL[wb + wlo], bl1 = WL[wb + whi];
            #pragma unroll
            for (int mt = 0; mt < 2; mt++) {
                MMAB(acc[mt][nt], ah[mt][0], ah[mt][1], ah[mt][2], ah[mt][3], bh0, bh1);
                MMAB(acc[mt][nt], ah[mt][0], ah[mt][1], ah[mt][2], ah[mt][3], bl0, bl1);
                MMAB(acc[mt][nt], al[mt][0], al[mt][1], al[mt][2], al[mt][3], bh0, bh1);
            }
        }
    }
}

// ---------------- K3: node projections ----------------
__global__ void __launch_bounds__(256, 4) k_node(
    const float* __restrict__ nodes,
    const float* __restrict__ bs, const float* __restrict__ br,
    const float* __restrict__ bm, const float* __restrict__ bf,
    float* __restrict__ out_self)
{
    extern __shared__ char sm[];
    int tx = threadIdx.x, w = tx >> 5, lane = tx & 31;
    int n0 = blockIdx.x * 128;

    const float4* nd4 = (const float4*)nodes;
    for (int i = tx; i < 128 * 16; i += 256) {
        int row = i >> 4, c4 = i & 15;
        float4 v = make_float4(0.f, 0.f, 0.f, 0.f);
        int gr = n0 + row;
        if (gr < N_NODES) v = nd4[(size_t)gr * 16 + c4];
        pack_A4(sm, row, c4, v);
    }
    float* sbias = (float*)(sm + OFS_AUX);
    if (tx < 64) {
        sbias[tx] = bs[tx]; sbias[64 + tx] = br[tx];
        sbias[128 + tx] = bm[tx]; sbias[192 + tx] = bf[tx];
    }

    float* olist[4] = {g_sent, g_recv, g_msg, out_self};
    int g = lane >> 2, q = lane & 3;
    int mtb = (w & 3) * 32, nb = (w >> 2) * 32;

    #pragma unroll
    for (int m = 0; m < 4; m++) {
        __syncthreads();
        for (int i = tx; i < W_WORDS / 4; i += 256) {
            ((uint4*)(sm + OFS_WH))[i] = ((const uint4*)&g_wpH[m][0])[i];
            ((uint4*)(sm + OFS_WL))[i] = ((const uint4*)&g_wpL[m][0])[i];
        }
        __syncthreads();

        float acc[2][4][4];
        mma_tile_smemA(sm, lane, w, acc);

        float* out = olist[m];
        const float* bi = sbias + m * 64;
        #pragma unroll
        for (int mt = 0; mt < 2; mt++) {
            int gr0 = n0 + mtb + mt * 16 + g;
            int gr1 = gr0 + 8;
            #pragma unroll
            for (int nt = 0; nt < 4; nt++) {
                int c = nb + nt * 8 + q * 2;
                float bx = bi[c], by = bi[c + 1];
                if (gr0 < N_NODES)
                    *(float2*)&out[(size_t)gr0 * 64 + c] =
                        make_float2(acc[mt][nt][0] + bx, acc[mt][nt][1] + by);
                if (gr1 < N_NODES)
                    *(float2*)&out[(size_t)gr1 * 64 + c] =
                        make_float2(acc[mt][nt][2] + bx, acc[mt][nt][3] + by);
            }
        }
    }
}

// ---------------- K4: edge GEMM (A direct, single 128-edge tile) ----------------
__global__ void __launch_bounds__(256, 4) k_edge(
    const float* __restrict__ edges,
    const int* __restrict__ senders, const int* __restrict__ receivers,
    const float* __restrict__ b_edge, const float* __restrict__ W_attn,
    const float* __restrict__ b_attn,
    float* __restrict__ edge_feat)
{
    extern __shared__ char sm[];
    int tx = threadIdx.x, w = tx >> 5, lane = tx & 31;
    int e0 = blockIdx.x * 128;

    float* sbw   = (float*)(sm + EOFS_AUX);        // [0:64) bias, [64:128) wa
    int*   ssend = (int*)(sm + EOFS_AUX + 512);
    int*   srecv = (int*)(sm + EOFS_AUX + 1024);

    if (tx < 128) {
        ssend[tx] = senders[e0 + tx];
        srecv[tx] = receivers[e0 + tx];
    }
    if (tx < 64) { sbw[tx] = b_edge[tx]; sbw[64 + tx] = W_attn[tx]; }
    for (int i = tx; i < W_WORDS / 4; i += 256) {
        ((uint4*)(sm + EOFS_WH))[i] = ((const uint4*)&g_wpH[4][0])[i];
        ((uint4*)(sm + EOFS_WL))[i] = ((const uint4*)&g_wpL[4][0])[i];
    }
    __syncthreads();

    const unsigned* WH = (const unsigned*)(sm + EOFS_WH);
    const unsigned* WL = (const unsigned*)(sm + EOFS_WL);
    const float2* eg2 = (const float2*)(edges + (size_t)e0 * 64);

    int g = lane >> 2, q = lane & 3;
    int s6 = g & 6;
    int wlo = q ^ s6, whi = (4 + q) ^ s6;
    int mtb = (w & 3) * 32, nb = (w >> 2) * 32;

    float acc[2][4][4];
    #pragma unroll
    for (int mt = 0; mt < 2; mt++)
        #pragma unroll
        for (int nt = 0; nt < 4; nt++)
            #pragma unroll
            for (int j = 0; j < 4; j++) acc[mt][nt][j] = 0.f;

    #pragma unroll
    for (int kt = 0; kt < 4; kt++) {
        unsigned ah[2][4], al[2][4];
        #pragma unroll
        for (int mt = 0; mt < 2; mt++) {
            int r0 = mtb + mt * 16 + g;
            int base = r0 * 32 + kt * 8 + q;
            float2 v00 = eg2[base];
            float2 v01 = eg2[base + 4];
            float2 v10 = eg2[base + 256];
            float2 v11 = eg2[base + 260];
            cvt2(v00, ah[mt][0], al[mt][0]);
            cvt2(v10, ah[mt][1], al[mt][1]);
            cvt2(v01, ah[mt][2], al[mt][2]);
            cvt2(v11, ah[mt][3], al[mt][3]);
        }
        #pragma unroll
        for (int nt = 0; nt < 4; nt++) {
            int n = nb + nt * 8 + g;
            int wb = kt * W_KT_STRIDE + n * 8;
            unsigned bh0 = WH[wb + wlo], bh1 = WH[wb + whi];
            unsigned bl0 = WL[wb + wlo], bl1 = WL[wb + whi];
            #pragma unroll
            for (int mt = 0; mt < 2; mt++) {
                MMAB(acc[mt][nt], ah[mt][0], ah[mt][1], ah[mt][2], ah[mt][3], bh0, bh1);
                MMAB(acc[mt][nt], ah[mt][0], ah[mt][1], ah[mt][2], ah[mt][3], bl0, bl1);
                MMAB(acc[mt][nt], al[mt][0], al[mt][1], al[mt][2], al[mt][3], bh0, bh1);
            }
        }
    }
    __syncthreads();                            // W frags dead; alias region as sD

    float* sD = (float*)(sm + EOFS_SD);         // 128 x 68
    #pragma unroll
    for (int mt = 0; mt < 2; mt++) {
        int r0 = mtb + mt * 16 + g;
        #pragma unroll
        for (int nt = 0; nt < 4; nt++) {
            int c = nb + nt * 8 + q * 2;
            *(float2*)&sD[r0 * 68 + c]       = make_float2(acc[mt][nt][0], acc[mt][nt][1]);
            *(float2*)&sD[(r0 + 8) * 68 + c] = make_float2(acc[mt][nt][2], acc[mt][nt][3]);
        }
    }
    __syncthreads();

    // 16 threads per row -> contiguous 256B gathers/stores per row
    int cr = tx & 15, rbase = tx >> 4;
    int c0 = cr * 4;
    float4 bi = *(float4*)&sbw[c0];
    float4 wa = *(float4*)&sbw[64 + c0];
    float battn = b_attn[0];

    #pragma unroll
    for (int i = 0; i < 8; i++) {
        int row = rbase + i * 16;
        int e = e0 + row;
        int s = ssend[row], r = srecv[row];
        float4 sv = *(const float4*)(g_sent + (size_t)s * 64 + c0);
        float4 rv = *(const float4*)(g_recv + (size_t)r * 64 + c0);
        float4 d  = *(const float4*)&sD[row * 68 + c0];

        float4 ef;
        ef.x = d.x + bi.x + sv.x + rv.x;
        ef.y = d.y + bi.y + sv.y + rv.y;
        ef.z = d.z + bi.z + sv.z + rv.z;
        ef.w = d.w + bi.w + sv.w + rv.w;
        *(float4*)&edge_feat[(size_t)e * 64 + c0] = ef;

        float p = ef.x * wa.x + ef.y * wa.y + ef.z * wa.z + ef.w * wa.w;
        p += __shfl_xor_sync(0xffffffffu, p, 1);
        p += __shfl_xor_sync(0xffffffffu, p, 2);
        p += __shfl_xor_sync(0xffffffffu, p, 4);
        p += __shfl_xor_sync(0xffffffffu, p, 8);
        if (cr == 0) {
            float l = p + battn;
            l = (l > 0.f) ? l : 0.01f * l;      // leaky_relu slope 0.01
            g_elogit[e] = __expf(l);            // max-free softmax (bounded logits)
            atomicAdd(&g_count[r], 1);
        }
    }
}

// ---------------- scan ----------------
__global__ void k_scan_a() {
    __shared__ int red[256];
    int b = blockIdx.x, t = threadIdx.x;
    red[t] = (t < SNPB) ? g_count[b * SNPB + t] : 0;
    __syncthreads();
    for (int off = 128; off; off >>= 1) {
        if (t < off) red[t] += red[t + off];
        __syncthreads();
    }
    if (t == 0) g_part[b] = red[0];
}
__global__ void k_scan_c() {
    __shared__ int sbase[256];
    __shared__ int sc[256];
    int b = blockIdx.x, t = threadIdx.x;
    sbase[t] = (t < b) ? g_part[t] : 0;
    __syncthreads();
    for (int off = 128; off; off >>= 1) {
        if (t < off) sbase[t] += sbase[t + off];
        __syncthreads();
    }
    int base = sbase[0];
    int idx = b * SNPB + t;
    int c = (t < SNPB) ? g_count[idx] : 0;
    sc[t] = c;
    __syncthreads();
    for (int off = 1; off < 256; off <<= 1) {
        int v = 0;
        if (t >= off) v = sc[t - off];
        __syncthreads();
        if (t >= off) sc[t] += v;
        __syncthreads();
    }
    if (t < SNPB) {
        int ro = base + sc[t] - c;
        g_rowoff[idx] = ro;
        g_cursor[idx] = ro;
    }
    if (b == SBLK - 1 && t == SNPB - 1) g_rowoff[N_NODES] = base + sc[t];
}

// ---------------- K7: CSR fill (packed sender+weight, one 8B store) ----------------
__global__ void k_fill(const int* __restrict__ senders,
                       const int* __restrict__ receivers) {
    int e = blockIdx.x * blockDim.x + threadIdx.x;
    if (e < N_EDGES) {
        int r = receivers[e];
        int s = senders[e];
        float w = g_elogit[e];
        int slot = atomicAdd(&g_cursor[r], 1);
        g_csr_sw[slot] = make_int2(s, __float_as_int(w));
    }
}

// ---------------- K8: warp-per-node aggregation (unrolled, packed CSR) ----------------
__global__ void k_aggregate(float* __restrict__ out_nodes)
{
    int gid = blockIdx.x * blockDim.x + threadIdx.x;
    int n = gid >> 5;
    if (n >= N_NODES) return;
    int lane = gid & 31;
    int off = g_rowoff[n];
    int deg = g_rowoff[n + 1] - off;

    int half = lane >> 4, quad = lane & 15;
    float4 acc = make_float4(0.f, 0.f, 0.f, 0.f);
    float sumex = 0.f;
    const float4* msg4 = (const float4*)g_msg;

    int t = half;
    for (; t + 2 < deg; t += 4) {          // two edges per iteration (MLP=2)
        int2 a = g_csr_sw[off + t];
        int2 b = g_csr_sw[off + t + 2];
        float exa = __int_as_float(a.y), exb = __int_as_float(b.y);
        float4 ma = msg4[(size_t)a.x * 16 + quad];
        float4 mb = msg4[(size_t)b.x * 16 + quad];
        acc.x += exa * ma.x + exb * mb.x;
        acc.y += exa * ma.y + exb * mb.y;
        acc.z += exa * ma.z + exb * mb.z;
        acc.w += exa * ma.w + exb * mb.w;
        if (quad == 0) sumex += exa + exb;
    }
    if (t < deg) {
        int2 a = g_csr_sw[off + t];
        float exa = __int_as_float(a.y);
        float4 ma = msg4[(size_t)a.x * 16 + quad];
        acc.x += exa * ma.x; acc.y += exa * ma.y;
        acc.z += exa * ma.z; acc.w += exa * ma.w;
        if (quad == 0) sumex += exa;
    }

    acc.x += __shfl_xor_sync(0xffffffffu, acc.x, 16);
    acc.y += __shfl_xor_sync(0xffffffffu, acc.y, 16);
    acc.z += __shfl_xor_sync(0xffffffffu, acc.z, 16);
    acc.w += __shfl_xor_sync(0xffffffffu, acc.w, 16);
    sumex += __shfl_xor_sync(0xffffffffu, sumex, 16);
    sumex = __shfl_sync(0xffffffffu, sumex, 0);

    if (lane < 16) {
        float inv = (deg > 0) ? (1.f / sumex) : 0.f;
        float4* o4 = (float4*)out_nodes;
        float4 o = o4[(size_t)n * 16 + lane];
        o.x += acc.x * inv; o.y += acc.y * inv;
        o.z += acc.z * inv; o.w += acc.w * inv;
        o4[(size_t)n * 16 + lane] = o;
    }
}

// ---------------- launch ----------------
extern "C" void kernel_launch(void* const* d_in, const int* in_sizes, int n_in,
                              void* d_out, int out_size)
{
    const float* nodes     = (const float*)d_in[0];
    const float* edges     = (const float*)d_in[1];
    const int*   senders   = (const int*)  d_in[2];
    const int*   receivers = (const int*)  d_in[3];
    const float* W_sent = (const float*)d_in[4];  const float* b_sent = (const float*)d_in[5];
    const float* W_recv = (const float*)d_in[6];  const float* b_recv = (const float*)d_in[7];
    const float* W_edge = (const float*)d_in[8];  const float* b_edge = (const float*)d_in[9];
    const float* W_attn = (const float*)d_in[10]; const float* b_attn = (const float*)d_in[11];
    const float* W_msg  = (const float*)d_in[12]; const float* b_msg  = (const float*)d_in[13];
    const float* W_self = (const float*)d_in[14]; const float* b_self = (const float*)d_in[15];

    float* out_nodes = (float*)d_out;
    float* edge_feat = out_nodes + (size_t)N_NODES * D;

    cudaFuncSetAttribute(k_node, cudaFuncAttributeMaxDynamicSharedMemorySize, NODE_SMEM);
    cudaFuncSetAttribute(k_edge, cudaFuncAttributeMaxDynamicSharedMemorySize, EDGE_SMEM);

    // launch #4 gets ncu-profiled -> keep k_edge there
    k_prep<<<5, 256>>>(W_sent, W_recv, W_msg, W_self, W_edge);      // 1
    k_init<<<(N_NODES + 255) / 256, 256>>>();                       // 2
    k_node<<<(N_NODES + 127) / 128, 256, NODE_SMEM>>>(              // 3
        nodes, b_sent, b_recv, b_msg, b_self, out_nodes);
    k_edge<<<N_EDGES / 128, 256, EDGE_SMEM>>>(                      // 4  <- profiled
        edges, senders, receivers, b_edge, W_attn, b_attn, edge_feat);
    k_scan_a<<<SBLK, 256>>>();                                      // 5
    k_scan_c<<<SBLK, 256>>>();                                      // 6
    k_fill<<<N_EDGES / 256, 256>>>(senders, receivers);             // 7
    k_aggregate<<<(N_NODES * 32 + 255) / 256, 256>>>(out_nodes);    // 8
}